// round 15
// baseline (speedup 1.0000x reference)
#include <cuda_runtime.h>
#include <cuda_fp16.h>
#include <math_constants.h>
#include <cstdint>

// ============================================================================
// DotProductAttention (B=8, Tq=Tk=2048, D=1024, fp32)
// Tensor-core GEMMs via mma.sync m16n8k16 with fp16 hi/lo fp32 emulation.
// Round-15: round-14 retry with FIXED GEMM2 N coverage (np<4 / nt<8; round 14
// only computed half of each warp's 64-col slab). GEMM1 = exact round-8.
// GEMM2 = BN=128, 256 threads, 8 warps of 32x64, 5 stages, 2 CTAs/SM.
// ============================================================================

#define NELEM (8u * 2048u * 1024u)
__device__ __half g_decH[NELEM];
__device__ __half g_decL[NELEM];
__device__ __half g_encH[NELEM];
__device__ __half g_encL[NELEM];
__device__ __half g_encTH[NELEM];         // [B, D, Tk]
__device__ __half g_wtsH[8u * 2048u * 2048u];

#define BM 128
#define BN 256
#define BK 32
#define LDA 40                              // halfs per smem row (80B pitch)
#define A_HALFS (128 * LDA)                 // 5120
#define B_HALFS (256 * LDA)                 // 10240
#define B2_HALFS (128 * LDA)                // 5120 (GEMM2 BN=128)

// ---------------------------------------------------------------------------
__device__ __forceinline__ uint32_t smem_u32(const void* p) {
    uint32_t a;
    asm("{ .reg .u64 t; cvta.to.shared.u64 t, %1; cvt.u32.u64 %0, t; }"
        : "=r"(a) : "l"(p));
    return a;
}
__device__ __forceinline__ void cp16(uint32_t dst, const void* src) {
    asm volatile("cp.async.cg.shared.global [%0], [%1], 16;"
                 :: "r"(dst), "l"(src) : "memory");
}
__device__ __forceinline__ void cp_commit() {
    asm volatile("cp.async.commit_group;" ::: "memory");
}
template <int N>
__device__ __forceinline__ void cp_wait() {
    asm volatile("cp.async.wait_group %0;" :: "n"(N) : "memory");
}
__device__ __forceinline__ void ldsm_x4(uint32_t& r0, uint32_t& r1,
                                        uint32_t& r2, uint32_t& r3, uint32_t addr) {
    asm volatile("ldmatrix.sync.aligned.m8n8.x4.shared.b16 {%0,%1,%2,%3}, [%4];"
                 : "=r"(r0), "=r"(r1), "=r"(r2), "=r"(r3) : "r"(addr));
}
__device__ __forceinline__ void mma16816(float* c, const uint32_t* a,
                                         uint32_t b0, uint32_t b1) {
    asm volatile(
        "mma.sync.aligned.m16n8k16.row.col.f32.f16.f16.f32 "
        "{%0,%1,%2,%3}, {%4,%5,%6,%7}, {%8,%9}, {%0,%1,%2,%3};"
        : "+f"(c[0]), "+f"(c[1]), "+f"(c[2]), "+f"(c[3])
        : "r"(a[0]), "r"(a[1]), "r"(a[2]), "r"(a[3]), "r"(b0), "r"(b1));
}

// ---------------------------------------------------------------------------
// GEMM1: C[M,N] = A[M,K] * B[N,K]^T, 3-term fp16 hi/lo (AhBh + AlBh + AhBl).
// 512 threads, 32x64 warp tiles, BK=32, 3 stages. EXACT round-8 (479us).
// ---------------------------------------------------------------------------
__global__ __launch_bounds__(512, 1)
void hmma_gemm1(const __half* __restrict__ AH, const __half* __restrict__ AL,
                const __half* __restrict__ BH, const __half* __restrict__ BL,
                float* __restrict__ C, int M, int N, int K)
{
    constexpr int NSTAGE = 3;
    constexpr uint32_t OFF_AH = 0;
    constexpr uint32_t OFF_AL = A_HALFS;
    constexpr uint32_t OFF_BH = 2 * A_HALFS;
    constexpr uint32_t OFF_BL = OFF_BH + B_HALFS;
    constexpr uint32_t STAGE_HALFS = 2 * A_HALFS + 2 * B_HALFS;

    extern __shared__ __half sm[];
    const uint32_t smBase = smem_u32(sm);

    const int t    = threadIdx.x;
    const int lane = t & 31;
    const int wid  = t >> 5;
    const int wm   = wid & 3;
    const int wn   = wid >> 2;

    const int bz = blockIdx.z;
    AH += (size_t)bz * M * K;
    AL += (size_t)bz * M * K;
    BH += (size_t)bz * N * K;
    BL += (size_t)bz * N * K;
    C  += (size_t)bz * M * N;
    const int m0 = blockIdx.y * BM;
    const int n0 = blockIdx.x * BN;

    const int lr = t >> 2;
    const int lc = t & 3;
    const uint32_t dA  = (uint32_t)(lr * LDA + lc * 8) * 2;
    const uint32_t dB0 = dA;
    const uint32_t dB1 = (uint32_t)((lr + 128) * LDA + lc * 8) * 2;
    const size_t gA  = (size_t)(m0 + lr) * K + lc * 8;
    const size_t gB0 = (size_t)(n0 + lr) * K + lc * 8;
    const size_t gB1 = (size_t)(n0 + lr + 128) * K + lc * 8;

    const uint32_t aOffB =
        (uint32_t)(((wm * 32 + (lane & 15)) * LDA + (lane >> 4) * 8) * 2);
    const uint32_t bOffB =
        (uint32_t)(((wn * 64 + ((lane >> 4) * 8) + (lane & 7)) * LDA +
                    ((lane >> 3) & 1) * 8) * 2);

    float acc[2][8][4];
#pragma unroll
    for (int i = 0; i < 2; i++)
#pragma unroll
        for (int j = 0; j < 8; j++)
#pragma unroll
            for (int q = 0; q < 4; q++) acc[i][j][q] = 0.0f;

    const int KB = K / BK;

    auto issue_stage = [&](int kb, int slot) {
        const uint32_t sb = smBase + (uint32_t)(slot * STAGE_HALFS * 2);
        const int ko = kb * BK;
        cp16(sb + OFF_AH * 2 + dA, AH + gA + ko);
        cp16(sb + OFF_AL * 2 + dA, AL + gA + ko);
        cp16(sb + OFF_BH * 2 + dB0, BH + gB0 + ko);
        cp16(sb + OFF_BH * 2 + dB1, BH + gB1 + ko);
        cp16(sb + OFF_BL * 2 + dB0, BL + gB0 + ko);
        cp16(sb + OFF_BL * 2 + dB1, BL + gB1 + ko);
    };

#pragma unroll
    for (int s = 0; s < NSTAGE - 1; s++) {
        issue_stage(s, s);
        cp_commit();
    }

    for (int kb = 0; kb < KB; kb++) {
        const int slot = kb % NSTAGE;
        cp_wait<NSTAGE - 2>();
        __syncthreads();

        const uint32_t sb = smBase + (uint32_t)(slot * STAGE_HALFS * 2);
        const uint32_t tAh = sb + OFF_AH * 2;
        const uint32_t tAl = sb + OFF_AL * 2;
        const uint32_t tBh = sb + OFF_BH * 2;
        const uint32_t tBl = sb + OFF_BL * 2;

#pragma unroll
        for (int ks = 0; ks < 2; ks++) {
            uint32_t ah[2][4], al[2][4];
#pragma unroll
            for (int mt = 0; mt < 2; mt++) {
                uint32_t ao = aOffB + (uint32_t)(mt * 16 * LDA * 2 + ks * 32);
                ldsm_x4(ah[mt][0], ah[mt][1], ah[mt][2], ah[mt][3], tAh + ao);
                ldsm_x4(al[mt][0], al[mt][1], al[mt][2], al[mt][3], tAl + ao);
            }
#pragma unroll
            for (int np = 0; np < 4; np++) {
                uint32_t bo = bOffB + (uint32_t)(np * 16 * LDA * 2 + ks * 32);
                uint32_t bh0, bh1, bh2, bh3, bl0, bl1, bl2, bl3;
                ldsm_x4(bh0, bh1, bh2, bh3, tBh + bo);
                ldsm_x4(bl0, bl1, bl2, bl3, tBl + bo);
#pragma unroll
                for (int mt = 0; mt < 2; mt++) {
                    mma16816(acc[mt][2 * np + 0], ah[mt], bh0, bh1);
                    mma16816(acc[mt][2 * np + 1], ah[mt], bh2, bh3);
                    mma16816(acc[mt][2 * np + 0], al[mt], bh0, bh1);
                    mma16816(acc[mt][2 * np + 1], al[mt], bh2, bh3);
                    mma16816(acc[mt][2 * np + 0], ah[mt], bl0, bl1);
                    mma16816(acc[mt][2 * np + 1], ah[mt], bl2, bl3);
                }
            }
        }

        const int nk = kb + NSTAGE - 1;
        if (nk < KB) issue_stage(nk, nk % NSTAGE);
        cp_commit();
    }

    const int row0 = m0 + wm * 32 + (lane >> 2);
    const int col0 = n0 + wn * 64 + 2 * (lane & 3);
#pragma unroll
    for (int mt = 0; mt < 2; mt++) {
#pragma unroll
        for (int nt = 0; nt < 8; nt++) {
            float* p0 = C + (size_t)(row0 + mt * 16) * N + col0 + nt * 8;
            float* p1 = C + (size_t)(row0 + mt * 16 + 8) * N + col0 + nt * 8;
            *(float2*)p0 = make_float2(acc[mt][nt][0], acc[mt][nt][1]);
            *(float2*)p1 = make_float2(acc[mt][nt][2], acc[mt][nt][3]);
        }
    }
}

// ---------------------------------------------------------------------------
// GEMM2: C[M,N] = A[M,K] * B[N,K]^T, 1 term (AhBh). BM=128, BN=128, BK=32,
// 5 stages, 256 threads (8 warps of 32x64: wm=wid&3, wn=wid>>2 in {0,1}),
// 2 CTAs per SM. FIXED: np<4 / nt<8 (full 64-col slab per warp).
// ---------------------------------------------------------------------------
__global__ __launch_bounds__(256, 2)
void hmma_gemm2(const __half* __restrict__ AH, const __half* __restrict__ BH,
                float* __restrict__ C, int M, int N, int K)
{
    constexpr int NSTAGE = 5;
    constexpr int BN2 = 128;
    constexpr uint32_t OFF_AH = 0;
    constexpr uint32_t OFF_BH = A_HALFS;
    constexpr uint32_t STAGE_HALFS = A_HALFS + B2_HALFS;   // 10240

    extern __shared__ __half sm[];
    const uint32_t smBase = smem_u32(sm);

    const int t    = threadIdx.x;
    const int lane = t & 31;
    const int wid  = t >> 5;          // 0..7
    const int wm   = wid & 3;         // 32-row slab
    const int wn   = wid >> 2;        // 64-col slab (0..1)

    const int bz = blockIdx.z;
    AH += (size_t)bz * M * K;
    BH += (size_t)bz * N * K;
    C  += (size_t)bz * M * N;
    const int m0 = blockIdx.y * BM;
    const int n0 = blockIdx.x * BN2;

    const int lr = t >> 2;            // 0..63
    const int lc = t & 3;
    const uint32_t dRow  = (uint32_t)(lr * LDA + lc * 8) * 2;
    const uint32_t dStep = (uint32_t)(64 * LDA) * 2;
    const size_t gA0 = (size_t)(m0 + lr) * K + lc * 8;
    const size_t gA1 = (size_t)(m0 + lr + 64) * K + lc * 8;
    const size_t gB0 = (size_t)(n0 + lr) * K + lc * 8;
    const size_t gB1 = (size_t)(n0 + lr + 64) * K + lc * 8;

    const uint32_t aOffB =
        (uint32_t)(((wm * 32 + (lane & 15)) * LDA + (lane >> 4) * 8) * 2);
    const uint32_t bOffB =
        (uint32_t)(((wn * 64 + ((lane >> 4) * 8) + (lane & 7)) * LDA +
                    ((lane >> 3) & 1) * 8) * 2);

    float acc[2][8][4];
#pragma unroll
    for (int i = 0; i < 2; i++)
#pragma unroll
        for (int j = 0; j < 8; j++)
#pragma unroll
            for (int q = 0; q < 4; q++) acc[i][j][q] = 0.0f;

    const int KB = K / BK;

    auto issue_stage = [&](int kb, int slot) {
        const uint32_t sb = smBase + (uint32_t)(slot * STAGE_HALFS * 2);
        const int ko = kb * BK;
        cp16(sb + OFF_AH * 2 + dRow,         AH + gA0 + ko);
        cp16(sb + OFF_AH * 2 + dRow + dStep, AH + gA1 + ko);
        cp16(sb + OFF_BH * 2 + dRow,         BH + gB0 + ko);
        cp16(sb + OFF_BH * 2 + dRow + dStep, BH + gB1 + ko);
    };

#pragma unroll
    for (int s = 0; s < NSTAGE - 1; s++) {
        issue_stage(s, s);
        cp_commit();
    }

    for (int kb = 0; kb < KB; kb++) {
        const int slot = kb % NSTAGE;
        cp_wait<NSTAGE - 2>();
        __syncthreads();

        const uint32_t sb = smBase + (uint32_t)(slot * STAGE_HALFS * 2);
        const uint32_t tAh = sb + OFF_AH * 2;
        const uint32_t tBh = sb + OFF_BH * 2;

#pragma unroll
        for (int ks = 0; ks < 2; ks++) {
            uint32_t ah[2][4];
#pragma unroll
            for (int mt = 0; mt < 2; mt++) {
                uint32_t ao = aOffB + (uint32_t)(mt * 16 * LDA * 2 + ks * 32);
                ldsm_x4(ah[mt][0], ah[mt][1], ah[mt][2], ah[mt][3], tAh + ao);
            }
#pragma unroll
            for (int np = 0; np < 4; np++) {
                uint32_t bo = bOffB + (uint32_t)(np * 16 * LDA * 2 + ks * 32);
                uint32_t bh0, bh1, bh2, bh3;
                ldsm_x4(bh0, bh1, bh2, bh3, tBh + bo);
#pragma unroll
                for (int mt = 0; mt < 2; mt++) {
                    mma16816(acc[mt][2 * np + 0], ah[mt], bh0, bh1);
                    mma16816(acc[mt][2 * np + 1], ah[mt], bh2, bh3);
                }
            }
        }

        const int nk = kb + NSTAGE - 1;
        if (nk < KB) issue_stage(nk, nk % NSTAGE);
        cp_commit();
    }

    const int row0 = m0 + wm * 32 + (lane >> 2);
    const int col0 = n0 + wn * 64 + 2 * (lane & 3);
#pragma unroll
    for (int mt = 0; mt < 2; mt++) {
#pragma unroll
        for (int nt = 0; nt < 8; nt++) {
            float* p0 = C + (size_t)(row0 + mt * 16) * N + col0 + nt * 8;
            float* p1 = C + (size_t)(row0 + mt * 16 + 8) * N + col0 + nt * 8;
            *(float2*)p0 = make_float2(acc[mt][nt][0], acc[mt][nt][1]);
            *(float2*)p1 = make_float2(acc[mt][nt][2], acc[mt][nt][3]);
        }
    }
}

// ---------------------------------------------------------------------------
__global__ __launch_bounds__(256)
void split_kernel(const float* __restrict__ in, __half* __restrict__ hi,
                  __half* __restrict__ lo, unsigned n4)
{
    unsigned i = blockIdx.x * 256u + threadIdx.x;
    if (i >= n4) return;
    float4 v = ((const float4*)in)[i];
    __half h0 = __float2half_rn(v.x), h1 = __float2half_rn(v.y);
    __half h2 = __float2half_rn(v.z), h3 = __float2half_rn(v.w);
    __half l0 = __float2half_rn(v.x - __half2float(h0));
    __half l1 = __float2half_rn(v.y - __half2float(h1));
    __half l2 = __float2half_rn(v.z - __half2float(h2));
    __half l3 = __float2half_rn(v.w - __half2float(h3));
    uint2 hp, lp;
    hp.x = (uint32_t)__half_as_ushort(h0) | ((uint32_t)__half_as_ushort(h1) << 16);
    hp.y = (uint32_t)__half_as_ushort(h2) | ((uint32_t)__half_as_ushort(h3) << 16);
    lp.x = (uint32_t)__half_as_ushort(l0) | ((uint32_t)__half_as_ushort(l1) << 16);
    lp.y = (uint32_t)__half_as_ushort(l2) | ((uint32_t)__half_as_ushort(l3) << 16);
    ((uint2*)hi)[i] = hp;
    ((uint2*)lo)[i] = lp;
}

// ---------------------------------------------------------------------------
__global__ __launch_bounds__(256)
void transpose_half_kernel(const float* __restrict__ in,
                           __half* __restrict__ outH, int R, int C)
{
    __shared__ float tb[32][33];
    const int bz = blockIdx.z;
    in += (size_t)bz * R * C;
    const size_t ob = (size_t)bz * R * C;
    const int c0 = blockIdx.x * 32;
    const int r0 = blockIdx.y * 32;
    const int tx = threadIdx.x & 31;
    const int ty = threadIdx.x >> 5;
#pragma unroll
    for (int j = 0; j < 32; j += 8)
        tb[ty + j][tx] = in[(size_t)(r0 + ty + j) * C + c0 + tx];
    __syncthreads();
#pragma unroll
    for (int j = 0; j < 32; j += 8) {
        float v = tb[tx][ty + j];
        outH[ob + (size_t)(c0 + ty + j) * R + r0 + tx] = __float2half_rn(v);
    }
}

// ---------------------------------------------------------------------------
__global__ __launch_bounds__(256)
void softmax_rows_kernel(float* __restrict__ W, __half* __restrict__ WH)
{
    const int Tk = 2048;
    const size_t base = (size_t)blockIdx.x * Tk;
    float4* p4 = (float4*)(W + base);
    uint2* ph2 = (uint2*)(WH + base);
    const int tid = threadIdx.x;

    __shared__ float red[8];

    float4 v0 = p4[tid];
    float4 v1 = p4[tid + 256];
    float m = fmaxf(fmaxf(fmaxf(v0.x, v0.y), fmaxf(v0.z, v0.w)),
                    fmaxf(fmaxf(v1.x, v1.y), fmaxf(v1.z, v1.w)));
#pragma unroll
    for (int o = 16; o; o >>= 1) m = fmaxf(m, __shfl_xor_sync(0xffffffffu, m, o));
    if ((tid & 31) == 0) red[tid >> 5] = m;
    __syncthreads();
    m = red[0];
#pragma unroll
    for (int w = 1; w < 8; w++) m = fmaxf(m, red[w]);
    __syncthreads();

    v0.x = __expf(v0.x - m); v0.y = __expf(v0.y - m);
    v0.z = __expf(v0.z - m); v0.w = __expf(v0.w - m);
    v1.x = __expf(v1.x - m); v1.y = __expf(v1.y - m);
    v1.z = __expf(v1.z - m); v1.w = __expf(v1.w - m);
    float s = (v0.x + v0.y) + (v0.z + v0.w) + (v1.x + v1.y) + (v1.z + v1.w);
#pragma unroll
    for (int o = 16; o; o >>= 1) s += __shfl_xor_sync(0xffffffffu, s, o);
    if ((tid & 31) == 0) red[tid >> 5] = s;
    __syncthreads();
    s = red[0];
#pragma unroll
    for (int w = 1; w < 8; w++) s += red[w];
    const float inv = 1.0f / s;

    v0.x *= inv; v0.y *= inv; v0.z *= inv; v0.w *= inv;
    v1.x *= inv; v1.y *= inv; v1.z *= inv; v1.w *= inv;
    p4[tid] = v0;
    p4[tid + 256] = v1;

    __half2 a0 = __floats2half2_rn(v0.x, v0.y);
    __half2 a1 = __floats2half2_rn(v0.z, v0.w);
    __half2 a2 = __floats2half2_rn(v1.x, v1.y);
    __half2 a3 = __floats2half2_rn(v1.z, v1.w);
    ph2[tid]       = make_uint2(*(uint32_t*)&a0, *(uint32_t*)&a1);
    ph2[tid + 256] = make_uint2(*(uint32_t*)&a2, *(uint32_t*)&a3);
}

// ---------------------------------------------------------------------------
extern "C" void kernel_launch(void* const* d_in, const int* in_sizes, int n_in,
                              void* d_out, int out_size)
{
    const float* dec = (const float*)d_in[0];  // [8, 2048, 1024]
    const float* enc = (const float*)d_in[1];  // [8, 2048, 1024]

    const int B = 8, Tq = 2048, Tk = 2048, D = 1024;

    float* ctx = (float*)d_out;                          // [B, Tq, D]
    float* wts = (float*)d_out + (size_t)B * Tq * D;     // [B, Tq, Tk]

    __half *decH, *decL, *encH, *encL, *encTH, *wtsH;
    cudaGetSymbolAddress((void**)&decH, g_decH);
    cudaGetSymbolAddress((void**)&decL, g_decL);
    cudaGetSymbolAddress((void**)&encH, g_encH);
    cudaGetSymbolAddress((void**)&encL, g_encL);
    cudaGetSymbolAddress((void**)&encTH, g_encTH);
    cudaGetSymbolAddress((void**)&wtsH, g_wtsH);

    constexpr int SMEM3 = 3 * (2 * A_HALFS + 2 * B_HALFS) * 2;  // 184320
    constexpr int SMEM2 = 5 * (A_HALFS + B2_HALFS) * 2;         // 102400
    cudaFuncSetAttribute((const void*)hmma_gemm1,
                         cudaFuncAttributeMaxDynamicSharedMemorySize, SMEM3);
    cudaFuncSetAttribute((const void*)hmma_gemm2,
                         cudaFuncAttributeMaxDynamicSharedMemorySize, SMEM2);

    const unsigned n4 = NELEM / 4;

    // 0) pre-split operands
    split_kernel<<<(n4 + 255) / 256, 256>>>(dec, decH, decL, n4);
    split_kernel<<<(n4 + 255) / 256, 256>>>(enc, encH, encL, n4);
    transpose_half_kernel<<<dim3(D / 32, Tk / 32, B), 256>>>(enc, encTH, Tk, D);

    // 1) scores = dec @ enc^T  (3-term)
    hmma_gemm1<<<dim3(Tk / BN, Tq / BM, B), 512, SMEM3>>>(
        decH, decL, encH, encL, wts, Tq, Tk, D);

    // 2) softmax in place (+ fp16 weights)
    softmax_rows_kernel<<<B * Tq, 256>>>(wts, wtsH);

    // 3) context = weights @ enc  (1-term, BN=128, 2 CTAs/SM, full N coverage)
    hmma_gemm2<<<dim3(D / 128, Tq / BM, B), 256, SMEM2>>>(
        wtsH, encTH, ctx, Tq, D, Tk);
}

// round 16
// speedup vs baseline: 1.4477x; 1.4477x over previous
#include <cuda_runtime.h>
#include <cuda_fp16.h>
#include <math_constants.h>
#include <cstdint>

// ============================================================================
// DotProductAttention (B=8, Tq=Tk=2048, D=1024, fp32)
// Tensor-core GEMMs via mma.sync m16n8k16 with fp16 hi/lo fp32 emulation.
// Round-16: EXACT revert to round-8 (best proven: 799.8us, rel_err 2.43e-4).
// GEMM1 = 3 terms (AhBh+AlBh+AhBl), 512 thr, 32x64 warp tiles, BK=32, 3-stage.
// GEMM2 = 1 term (WhEh), 512 thr, 32x64 warp tiles, BK=32, 5-stage.
// Round-15 showed a ~1.57x clock throttle (identical GEMM1 code: 479->753us
// at equal tensor%); this revert re-baselines.
// ============================================================================

#define NELEM (8u * 2048u * 1024u)
__device__ __half g_decH[NELEM];
__device__ __half g_decL[NELEM];
__device__ __half g_encH[NELEM];
__device__ __half g_encL[NELEM];
__device__ __half g_encTH[NELEM];         // [B, D, Tk]
__device__ __half g_wtsH[8u * 2048u * 2048u];

#define BM 128
#define BN 256
#define BK 32
#define LDA 40                              // halfs per smem row (80B pitch)
#define A_HALFS (128 * LDA)                 // 5120
#define B_HALFS (256 * LDA)                 // 10240

// ---------------------------------------------------------------------------
__device__ __forceinline__ uint32_t smem_u32(const void* p) {
    uint32_t a;
    asm("{ .reg .u64 t; cvta.to.shared.u64 t, %1; cvt.u32.u64 %0, t; }"
        : "=r"(a) : "l"(p));
    return a;
}
__device__ __forceinline__ void cp16(uint32_t dst, const void* src) {
    asm volatile("cp.async.cg.shared.global [%0], [%1], 16;"
                 :: "r"(dst), "l"(src) : "memory");
}
__device__ __forceinline__ void cp_commit() {
    asm volatile("cp.async.commit_group;" ::: "memory");
}
template <int N>
__device__ __forceinline__ void cp_wait() {
    asm volatile("cp.async.wait_group %0;" :: "n"(N) : "memory");
}
__device__ __forceinline__ void ldsm_x4(uint32_t& r0, uint32_t& r1,
                                        uint32_t& r2, uint32_t& r3, uint32_t addr) {
    asm volatile("ldmatrix.sync.aligned.m8n8.x4.shared.b16 {%0,%1,%2,%3}, [%4];"
                 : "=r"(r0), "=r"(r1), "=r"(r2), "=r"(r3) : "r"(addr));
}
__device__ __forceinline__ void mma16816(float* c, const uint32_t* a,
                                         uint32_t b0, uint32_t b1) {
    asm volatile(
        "mma.sync.aligned.m16n8k16.row.col.f32.f16.f16.f32 "
        "{%0,%1,%2,%3}, {%4,%5,%6,%7}, {%8,%9}, {%0,%1,%2,%3};"
        : "+f"(c[0]), "+f"(c[1]), "+f"(c[2]), "+f"(c[3])
        : "r"(a[0]), "r"(a[1]), "r"(a[2]), "r"(a[3]), "r"(b0), "r"(b1));
}

// ---------------------------------------------------------------------------
// NT GEMM: C[M,N] = A[M,K] * B[N,K]^T, fp16 hi/lo operands.
// NTERMS=3: AhBh + AlBh + AhBl (stage = Ah,Al,Bh,Bl).
// NTERMS=1: AhBh             (stage = Ah,Bh).
// grid = (N/256, M/128, batch), 512 threads.
// ---------------------------------------------------------------------------
template <int NTERMS, int NSTAGE>
__global__ __launch_bounds__(512, 1)
void hmma_gemm_nt_f16(const __half* __restrict__ AH, const __half* __restrict__ AL,
                      const __half* __restrict__ BH, const __half* __restrict__ BL,
                      float* __restrict__ C, int M, int N, int K)
{
    constexpr uint32_t OFF_AH = 0;
    constexpr uint32_t OFF_AL = A_HALFS;                           // 3-term only
    constexpr uint32_t OFF_BH = (NTERMS == 3) ? 2 * A_HALFS : A_HALFS;
    constexpr uint32_t OFF_BL = OFF_BH + B_HALFS;                  // 3-term only
    constexpr uint32_t STAGE_HALFS =
        (NTERMS == 3) ? (2 * A_HALFS + 2 * B_HALFS) : (A_HALFS + B_HALFS);

    extern __shared__ __half sm[];
    const uint32_t smBase = smem_u32(sm);

    const int t    = threadIdx.x;
    const int lane = t & 31;
    const int wid  = t >> 5;
    const int wm   = wid & 3;    // 32-row slab
    const int wn   = wid >> 2;   // 64-col slab (0..3)

    const int bz = blockIdx.z;
    AH += (size_t)bz * M * K;
    BH += (size_t)bz * N * K;
    if (NTERMS == 3) { AL += (size_t)bz * M * K; BL += (size_t)bz * N * K; }
    C += (size_t)bz * M * N;
    const int m0 = blockIdx.y * BM;
    const int n0 = blockIdx.x * BN;

    const int lr = t >> 2;
    const int lc = t & 3;
    const uint32_t dA  = (uint32_t)(lr * LDA + lc * 8) * 2;
    const uint32_t dB0 = dA;
    const uint32_t dB1 = (uint32_t)((lr + 128) * LDA + lc * 8) * 2;
    const size_t gA  = (size_t)(m0 + lr) * K + lc * 8;
    const size_t gB0 = (size_t)(n0 + lr) * K + lc * 8;
    const size_t gB1 = (size_t)(n0 + lr + 128) * K + lc * 8;

    const uint32_t aOffB =
        (uint32_t)(((wm * 32 + (lane & 15)) * LDA + (lane >> 4) * 8) * 2);
    const uint32_t bOffB =
        (uint32_t)(((wn * 64 + ((lane >> 4) * 8) + (lane & 7)) * LDA +
                    ((lane >> 3) & 1) * 8) * 2);

    float acc[2][8][4];
#pragma unroll
    for (int i = 0; i < 2; i++)
#pragma unroll
        for (int j = 0; j < 8; j++)
#pragma unroll
            for (int q = 0; q < 4; q++) acc[i][j][q] = 0.0f;

    const int KB = K / BK;

    auto issue_stage = [&](int kb, int slot) {
        const uint32_t sb = smBase + (uint32_t)(slot * STAGE_HALFS * 2);
        const int ko = kb * BK;
        cp16(sb + OFF_AH * 2 + dA, AH + gA + ko);
        if (NTERMS == 3) cp16(sb + OFF_AL * 2 + dA, AL + gA + ko);
        cp16(sb + OFF_BH * 2 + dB0, BH + gB0 + ko);
        cp16(sb + OFF_BH * 2 + dB1, BH + gB1 + ko);
        if (NTERMS == 3) {
            cp16(sb + OFF_BL * 2 + dB0, BL + gB0 + ko);
            cp16(sb + OFF_BL * 2 + dB1, BL + gB1 + ko);
        }
    };

#pragma unroll
    for (int s = 0; s < NSTAGE - 1; s++) {
        issue_stage(s, s);
        cp_commit();
    }

    for (int kb = 0; kb < KB; kb++) {
        const int slot = kb % NSTAGE;
        cp_wait<NSTAGE - 2>();
        __syncthreads();

        const uint32_t sb = smBase + (uint32_t)(slot * STAGE_HALFS * 2);
        const uint32_t tAh = sb + OFF_AH * 2;
        const uint32_t tAl = sb + OFF_AL * 2;
        const uint32_t tBh = sb + OFF_BH * 2;
        const uint32_t tBl = sb + OFF_BL * 2;

#pragma unroll
        for (int ks = 0; ks < 2; ks++) {
            uint32_t ah[2][4], al[2][4];
#pragma unroll
            for (int mt = 0; mt < 2; mt++) {
                uint32_t ao = aOffB + (uint32_t)(mt * 16 * LDA * 2 + ks * 32);
                ldsm_x4(ah[mt][0], ah[mt][1], ah[mt][2], ah[mt][3], tAh + ao);
                if (NTERMS == 3)
                    ldsm_x4(al[mt][0], al[mt][1], al[mt][2], al[mt][3], tAl + ao);
            }
#pragma unroll
            for (int np = 0; np < 4; np++) {
                uint32_t bo = bOffB + (uint32_t)(np * 16 * LDA * 2 + ks * 32);
                uint32_t bh0, bh1, bh2, bh3, bl0, bl1, bl2, bl3;
                ldsm_x4(bh0, bh1, bh2, bh3, tBh + bo);
                if (NTERMS == 3)
                    ldsm_x4(bl0, bl1, bl2, bl3, tBl + bo);  // paired with Bh
#pragma unroll
                for (int mt = 0; mt < 2; mt++) {
                    mma16816(acc[mt][2 * np + 0], ah[mt], bh0, bh1);
                    mma16816(acc[mt][2 * np + 1], ah[mt], bh2, bh3);
                    if (NTERMS == 3) {
                        mma16816(acc[mt][2 * np + 0], al[mt], bh0, bh1);
                        mma16816(acc[mt][2 * np + 1], al[mt], bh2, bh3);
                        mma16816(acc[mt][2 * np + 0], ah[mt], bl0, bl1);
                        mma16816(acc[mt][2 * np + 1], ah[mt], bl2, bl3);
                    }
                }
            }
        }

        const int nk = kb + NSTAGE - 1;
        if (nk < KB) issue_stage(nk, nk % NSTAGE);
        cp_commit();
    }

    const int row0 = m0 + wm * 32 + (lane >> 2);
    const int col0 = n0 + wn * 64 + 2 * (lane & 3);
#pragma unroll
    for (int mt = 0; mt < 2; mt++) {
#pragma unroll
        for (int nt = 0; nt < 8; nt++) {
            float* p0 = C + (size_t)(row0 + mt * 16) * N + col0 + nt * 8;
            float* p1 = C + (size_t)(row0 + mt * 16 + 8) * N + col0 + nt * 8;
            *(float2*)p0 = make_float2(acc[mt][nt][0], acc[mt][nt][1]);
            *(float2*)p1 = make_float2(acc[mt][nt][2], acc[mt][nt][3]);
        }
    }
}

// ---------------------------------------------------------------------------
__global__ __launch_bounds__(256)
void split_kernel(const float* __restrict__ in, __half* __restrict__ hi,
                  __half* __restrict__ lo, unsigned n4)
{
    unsigned i = blockIdx.x * 256u + threadIdx.x;
    if (i >= n4) return;
    float4 v = ((const float4*)in)[i];
    __half h0 = __float2half_rn(v.x), h1 = __float2half_rn(v.y);
    __half h2 = __float2half_rn(v.z), h3 = __float2half_rn(v.w);
    __half l0 = __float2half_rn(v.x - __half2float(h0));
    __half l1 = __float2half_rn(v.y - __half2float(h1));
    __half l2 = __float2half_rn(v.z - __half2float(h2));
    __half l3 = __float2half_rn(v.w - __half2float(h3));
    uint2 hp, lp;
    hp.x = (uint32_t)__half_as_ushort(h0) | ((uint32_t)__half_as_ushort(h1) << 16);
    hp.y = (uint32_t)__half_as_ushort(h2) | ((uint32_t)__half_as_ushort(h3) << 16);
    lp.x = (uint32_t)__half_as_ushort(l0) | ((uint32_t)__half_as_ushort(l1) << 16);
    lp.y = (uint32_t)__half_as_ushort(l2) | ((uint32_t)__half_as_ushort(l3) << 16);
    ((uint2*)hi)[i] = hp;
    ((uint2*)lo)[i] = lp;
}

// ---------------------------------------------------------------------------
__global__ __launch_bounds__(256)
void transpose_half_kernel(const float* __restrict__ in,
                           __half* __restrict__ outH, int R, int C)
{
    __shared__ float tb[32][33];
    const int bz = blockIdx.z;
    in += (size_t)bz * R * C;
    const size_t ob = (size_t)bz * R * C;
    const int c0 = blockIdx.x * 32;
    const int r0 = blockIdx.y * 32;
    const int tx = threadIdx.x & 31;
    const int ty = threadIdx.x >> 5;
#pragma unroll
    for (int j = 0; j < 32; j += 8)
        tb[ty + j][tx] = in[(size_t)(r0 + ty + j) * C + c0 + tx];
    __syncthreads();
#pragma unroll
    for (int j = 0; j < 32; j += 8) {
        float v = tb[tx][ty + j];
        outH[ob + (size_t)(c0 + ty + j) * R + r0 + tx] = __float2half_rn(v);
    }
}

// ---------------------------------------------------------------------------
__global__ __launch_bounds__(256)
void softmax_rows_kernel(float* __restrict__ W, __half* __restrict__ WH)
{
    const int Tk = 2048;
    const size_t base = (size_t)blockIdx.x * Tk;
    float4* p4 = (float4*)(W + base);
    uint2* ph2 = (uint2*)(WH + base);
    const int tid = threadIdx.x;

    __shared__ float red[8];

    float4 v0 = p4[tid];
    float4 v1 = p4[tid + 256];
    float m = fmaxf(fmaxf(fmaxf(v0.x, v0.y), fmaxf(v0.z, v0.w)),
                    fmaxf(fmaxf(v1.x, v1.y), fmaxf(v1.z, v1.w)));
#pragma unroll
    for (int o = 16; o; o >>= 1) m = fmaxf(m, __shfl_xor_sync(0xffffffffu, m, o));
    if ((tid & 31) == 0) red[tid >> 5] = m;
    __syncthreads();
    m = red[0];
#pragma unroll
    for (int w = 1; w < 8; w++) m = fmaxf(m, red[w]);
    __syncthreads();

    v0.x = __expf(v0.x - m); v0.y = __expf(v0.y - m);
    v0.z = __expf(v0.z - m); v0.w = __expf(v0.w - m);
    v1.x = __expf(v1.x - m); v1.y = __expf(v1.y - m);
    v1.z = __expf(v1.z - m); v1.w = __expf(v1.w - m);
    float s = (v0.x + v0.y) + (v0.z + v0.w) + (v1.x + v1.y) + (v1.z + v1.w);
#pragma unroll
    for (int o = 16; o; o >>= 1) s += __shfl_xor_sync(0xffffffffu, s, o);
    if ((tid & 31) == 0) red[tid >> 5] = s;
    __syncthreads();
    s = red[0];
#pragma unroll
    for (int w = 1; w < 8; w++) s += red[w];
    const float inv = 1.0f / s;

    v0.x *= inv; v0.y *= inv; v0.z *= inv; v0.w *= inv;
    v1.x *= inv; v1.y *= inv; v1.z *= inv; v1.w *= inv;
    p4[tid] = v0;
    p4[tid + 256] = v1;

    __half2 a0 = __floats2half2_rn(v0.x, v0.y);
    __half2 a1 = __floats2half2_rn(v0.z, v0.w);
    __half2 a2 = __floats2half2_rn(v1.x, v1.y);
    __half2 a3 = __floats2half2_rn(v1.z, v1.w);
    ph2[tid]       = make_uint2(*(uint32_t*)&a0, *(uint32_t*)&a1);
    ph2[tid + 256] = make_uint2(*(uint32_t*)&a2, *(uint32_t*)&a3);
}

// ---------------------------------------------------------------------------
extern "C" void kernel_launch(void* const* d_in, const int* in_sizes, int n_in,
                              void* d_out, int out_size)
{
    const float* dec = (const float*)d_in[0];  // [8, 2048, 1024]
    const float* enc = (const float*)d_in[1];  // [8, 2048, 1024]

    const int B = 8, Tq = 2048, Tk = 2048, D = 1024;

    float* ctx = (float*)d_out;                          // [B, Tq, D]
    float* wts = (float*)d_out + (size_t)B * Tq * D;     // [B, Tq, Tk]

    __half *decH, *decL, *encH, *encL, *encTH, *wtsH;
    cudaGetSymbolAddress((void**)&decH, g_decH);
    cudaGetSymbolAddress((void**)&decL, g_decL);
    cudaGetSymbolAddress((void**)&encH, g_encH);
    cudaGetSymbolAddress((void**)&encL, g_encL);
    cudaGetSymbolAddress((void**)&encTH, g_encTH);
    cudaGetSymbolAddress((void**)&wtsH, g_wtsH);

    constexpr int SMEM3 = 3 * (2 * A_HALFS + 2 * B_HALFS) * 2;  // 184320
    constexpr int SMEM1 = 5 * (A_HALFS + B_HALFS) * 2;          // 153600
    cudaFuncSetAttribute((const void*)hmma_gemm_nt_f16<3, 3>,
                         cudaFuncAttributeMaxDynamicSharedMemorySize, SMEM3);
    cudaFuncSetAttribute((const void*)hmma_gemm_nt_f16<1, 5>,
                         cudaFuncAttributeMaxDynamicSharedMemorySize, SMEM1);

    const unsigned n4 = NELEM / 4;

    // 0) pre-split operands
    split_kernel<<<(n4 + 255) / 256, 256>>>(dec, decH, decL, n4);
    split_kernel<<<(n4 + 255) / 256, 256>>>(enc, encH, encL, n4);
    transpose_half_kernel<<<dim3(D / 32, Tk / 32, B), 256>>>(enc, encTH, Tk, D);

    // 1) scores = dec @ enc^T  (3-term)
    hmma_gemm_nt_f16<3, 3><<<dim3(Tk / BN, Tq / BM, B), 512, SMEM3>>>(
        decH, decL, encH, encL, wts, Tq, Tk, D);

    // 2) softmax in place (+ fp16 weights)
    softmax_rows_kernel<<<B * Tq, 256>>>(wts, wtsH);

    // 3) context = weights @ enc  (1-term)
    hmma_gemm_nt_f16<1, 5><<<dim3(D / BN, Tq / BM, B), 512, SMEM1>>>(
        wtsH, nullptr, encTH, nullptr, ctx, Tq, D, Tk);
}

// round 17
// speedup vs baseline: 1.4897x; 1.0290x over previous
#include <cuda_runtime.h>
#include <cuda_fp16.h>
#include <math_constants.h>
#include <cstdint>

// ============================================================================
// DotProductAttention (B=8, Tq=Tk=2048, D=1024, fp32)
// Tensor-core GEMMs via mma.sync m16n8k16 with fp16 hi/lo fp32 emulation.
// Round-17: clean retest of round-15 under normal clocks (round-15 ran on a
// ~1.57x-throttled chip; normalized numbers suggested its GEMM2 helped).
// GEMM1 = exact round-8 (479us/71.5%). GEMM2 = 1 term, BN=128, 256 threads,
// 8 warps of 32x64, 5 stages, 2 CTAs/SM (launch_bounds(256,2)).
// ============================================================================

#define NELEM (8u * 2048u * 1024u)
__device__ __half g_decH[NELEM];
__device__ __half g_decL[NELEM];
__device__ __half g_encH[NELEM];
__device__ __half g_encL[NELEM];
__device__ __half g_encTH[NELEM];         // [B, D, Tk]
__device__ __half g_wtsH[8u * 2048u * 2048u];

#define BM 128
#define BN 256
#define BK 32
#define LDA 40                              // halfs per smem row (80B pitch)
#define A_HALFS (128 * LDA)                 // 5120
#define B_HALFS (256 * LDA)                 // 10240
#define B2_HALFS (128 * LDA)                // 5120 (GEMM2 BN=128)

// ---------------------------------------------------------------------------
__device__ __forceinline__ uint32_t smem_u32(const void* p) {
    uint32_t a;
    asm("{ .reg .u64 t; cvta.to.shared.u64 t, %1; cvt.u32.u64 %0, t; }"
        : "=r"(a) : "l"(p));
    return a;
}
__device__ __forceinline__ void cp16(uint32_t dst, const void* src) {
    asm volatile("cp.async.cg.shared.global [%0], [%1], 16;"
                 :: "r"(dst), "l"(src) : "memory");
}
__device__ __forceinline__ void cp_commit() {
    asm volatile("cp.async.commit_group;" ::: "memory");
}
template <int N>
__device__ __forceinline__ void cp_wait() {
    asm volatile("cp.async.wait_group %0;" :: "n"(N) : "memory");
}
__device__ __forceinline__ void ldsm_x4(uint32_t& r0, uint32_t& r1,
                                        uint32_t& r2, uint32_t& r3, uint32_t addr) {
    asm volatile("ldmatrix.sync.aligned.m8n8.x4.shared.b16 {%0,%1,%2,%3}, [%4];"
                 : "=r"(r0), "=r"(r1), "=r"(r2), "=r"(r3) : "r"(addr));
}
__device__ __forceinline__ void mma16816(float* c, const uint32_t* a,
                                         uint32_t b0, uint32_t b1) {
    asm volatile(
        "mma.sync.aligned.m16n8k16.row.col.f32.f16.f16.f32 "
        "{%0,%1,%2,%3}, {%4,%5,%6,%7}, {%8,%9}, {%0,%1,%2,%3};"
        : "+f"(c[0]), "+f"(c[1]), "+f"(c[2]), "+f"(c[3])
        : "r"(a[0]), "r"(a[1]), "r"(a[2]), "r"(a[3]), "r"(b0), "r"(b1));
}

// ---------------------------------------------------------------------------
// GEMM1: C[M,N] = A[M,K] * B[N,K]^T, 3-term fp16 hi/lo (AhBh + AlBh + AhBl).
// 512 threads, 32x64 warp tiles, BK=32, 3 stages. EXACT round-8 (479us).
// ---------------------------------------------------------------------------
__global__ __launch_bounds__(512, 1)
void hmma_gemm1(const __half* __restrict__ AH, const __half* __restrict__ AL,
                const __half* __restrict__ BH, const __half* __restrict__ BL,
                float* __restrict__ C, int M, int N, int K)
{
    constexpr int NSTAGE = 3;
    constexpr uint32_t OFF_AH = 0;
    constexpr uint32_t OFF_AL = A_HALFS;
    constexpr uint32_t OFF_BH = 2 * A_HALFS;
    constexpr uint32_t OFF_BL = OFF_BH + B_HALFS;
    constexpr uint32_t STAGE_HALFS = 2 * A_HALFS + 2 * B_HALFS;

    extern __shared__ __half sm[];
    const uint32_t smBase = smem_u32(sm);

    const int t    = threadIdx.x;
    const int lane = t & 31;
    const int wid  = t >> 5;
    const int wm   = wid & 3;
    const int wn   = wid >> 2;

    const int bz = blockIdx.z;
    AH += (size_t)bz * M * K;
    AL += (size_t)bz * M * K;
    BH += (size_t)bz * N * K;
    BL += (size_t)bz * N * K;
    C  += (size_t)bz * M * N;
    const int m0 = blockIdx.y * BM;
    const int n0 = blockIdx.x * BN;

    const int lr = t >> 2;
    const int lc = t & 3;
    const uint32_t dA  = (uint32_t)(lr * LDA + lc * 8) * 2;
    const uint32_t dB0 = dA;
    const uint32_t dB1 = (uint32_t)((lr + 128) * LDA + lc * 8) * 2;
    const size_t gA  = (size_t)(m0 + lr) * K + lc * 8;
    const size_t gB0 = (size_t)(n0 + lr) * K + lc * 8;
    const size_t gB1 = (size_t)(n0 + lr + 128) * K + lc * 8;

    const uint32_t aOffB =
        (uint32_t)(((wm * 32 + (lane & 15)) * LDA + (lane >> 4) * 8) * 2);
    const uint32_t bOffB =
        (uint32_t)(((wn * 64 + ((lane >> 4) * 8) + (lane & 7)) * LDA +
                    ((lane >> 3) & 1) * 8) * 2);

    float acc[2][8][4];
#pragma unroll
    for (int i = 0; i < 2; i++)
#pragma unroll
        for (int j = 0; j < 8; j++)
#pragma unroll
            for (int q = 0; q < 4; q++) acc[i][j][q] = 0.0f;

    const int KB = K / BK;

    auto issue_stage = [&](int kb, int slot) {
        const uint32_t sb = smBase + (uint32_t)(slot * STAGE_HALFS * 2);
        const int ko = kb * BK;
        cp16(sb + OFF_AH * 2 + dA, AH + gA + ko);
        cp16(sb + OFF_AL * 2 + dA, AL + gA + ko);
        cp16(sb + OFF_BH * 2 + dB0, BH + gB0 + ko);
        cp16(sb + OFF_BH * 2 + dB1, BH + gB1 + ko);
        cp16(sb + OFF_BL * 2 + dB0, BL + gB0 + ko);
        cp16(sb + OFF_BL * 2 + dB1, BL + gB1 + ko);
    };

#pragma unroll
    for (int s = 0; s < NSTAGE - 1; s++) {
        issue_stage(s, s);
        cp_commit();
    }

    for (int kb = 0; kb < KB; kb++) {
        const int slot = kb % NSTAGE;
        cp_wait<NSTAGE - 2>();
        __syncthreads();

        const uint32_t sb = smBase + (uint32_t)(slot * STAGE_HALFS * 2);
        const uint32_t tAh = sb + OFF_AH * 2;
        const uint32_t tAl = sb + OFF_AL * 2;
        const uint32_t tBh = sb + OFF_BH * 2;
        const uint32_t tBl = sb + OFF_BL * 2;

#pragma unroll
        for (int ks = 0; ks < 2; ks++) {
            uint32_t ah[2][4], al[2][4];
#pragma unroll
            for (int mt = 0; mt < 2; mt++) {
                uint32_t ao = aOffB + (uint32_t)(mt * 16 * LDA * 2 + ks * 32);
                ldsm_x4(ah[mt][0], ah[mt][1], ah[mt][2], ah[mt][3], tAh + ao);
                ldsm_x4(al[mt][0], al[mt][1], al[mt][2], al[mt][3], tAl + ao);
            }
#pragma unroll
            for (int np = 0; np < 4; np++) {
                uint32_t bo = bOffB + (uint32_t)(np * 16 * LDA * 2 + ks * 32);
                uint32_t bh0, bh1, bh2, bh3, bl0, bl1, bl2, bl3;
                ldsm_x4(bh0, bh1, bh2, bh3, tBh + bo);
                ldsm_x4(bl0, bl1, bl2, bl3, tBl + bo);
#pragma unroll
                for (int mt = 0; mt < 2; mt++) {
                    mma16816(acc[mt][2 * np + 0], ah[mt], bh0, bh1);
                    mma16816(acc[mt][2 * np + 1], ah[mt], bh2, bh3);
                    mma16816(acc[mt][2 * np + 0], al[mt], bh0, bh1);
                    mma16816(acc[mt][2 * np + 1], al[mt], bh2, bh3);
                    mma16816(acc[mt][2 * np + 0], ah[mt], bl0, bl1);
                    mma16816(acc[mt][2 * np + 1], ah[mt], bl2, bl3);
                }
            }
        }

        const int nk = kb + NSTAGE - 1;
        if (nk < KB) issue_stage(nk, nk % NSTAGE);
        cp_commit();
    }

    const int row0 = m0 + wm * 32 + (lane >> 2);
    const int col0 = n0 + wn * 64 + 2 * (lane & 3);
#pragma unroll
    for (int mt = 0; mt < 2; mt++) {
#pragma unroll
        for (int nt = 0; nt < 8; nt++) {
            float* p0 = C + (size_t)(row0 + mt * 16) * N + col0 + nt * 8;
            float* p1 = C + (size_t)(row0 + mt * 16 + 8) * N + col0 + nt * 8;
            *(float2*)p0 = make_float2(acc[mt][nt][0], acc[mt][nt][1]);
            *(float2*)p1 = make_float2(acc[mt][nt][2], acc[mt][nt][3]);
        }
    }
}

// ---------------------------------------------------------------------------
// GEMM2: C[M,N] = A[M,K] * B[N,K]^T, 1 term (AhBh). BM=128, BN=128, BK=32,
// 5 stages, 256 threads (8 warps of 32x64: wm=wid&3, wn=wid>>2 in {0,1}),
// 2 CTAs per SM. Full N coverage (np<4, nt<8).
// ---------------------------------------------------------------------------
__global__ __launch_bounds__(256, 2)
void hmma_gemm2(const __half* __restrict__ AH, const __half* __restrict__ BH,
                float* __restrict__ C, int M, int N, int K)
{
    constexpr int NSTAGE = 5;
    constexpr int BN2 = 128;
    constexpr uint32_t OFF_AH = 0;
    constexpr uint32_t OFF_BH = A_HALFS;
    constexpr uint32_t STAGE_HALFS = A_HALFS + B2_HALFS;   // 10240

    extern __shared__ __half sm[];
    const uint32_t smBase = smem_u32(sm);

    const int t    = threadIdx.x;
    const int lane = t & 31;
    const int wid  = t >> 5;          // 0..7
    const int wm   = wid & 3;         // 32-row slab
    const int wn   = wid >> 2;        // 64-col slab (0..1)

    const int bz = blockIdx.z;
    AH += (size_t)bz * M * K;
    BH += (size_t)bz * N * K;
    C  += (size_t)bz * M * N;
    const int m0 = blockIdx.y * BM;
    const int n0 = blockIdx.x * BN2;

    const int lr = t >> 2;            // 0..63
    const int lc = t & 3;
    const uint32_t dRow  = (uint32_t)(lr * LDA + lc * 8) * 2;
    const uint32_t dStep = (uint32_t)(64 * LDA) * 2;
    const size_t gA0 = (size_t)(m0 + lr) * K + lc * 8;
    const size_t gA1 = (size_t)(m0 + lr + 64) * K + lc * 8;
    const size_t gB0 = (size_t)(n0 + lr) * K + lc * 8;
    const size_t gB1 = (size_t)(n0 + lr + 64) * K + lc * 8;

    const uint32_t aOffB =
        (uint32_t)(((wm * 32 + (lane & 15)) * LDA + (lane >> 4) * 8) * 2);
    const uint32_t bOffB =
        (uint32_t)(((wn * 64 + ((lane >> 4) * 8) + (lane & 7)) * LDA +
                    ((lane >> 3) & 1) * 8) * 2);

    float acc[2][8][4];
#pragma unroll
    for (int i = 0; i < 2; i++)
#pragma unroll
        for (int j = 0; j < 8; j++)
#pragma unroll
            for (int q = 0; q < 4; q++) acc[i][j][q] = 0.0f;

    const int KB = K / BK;

    auto issue_stage = [&](int kb, int slot) {
        const uint32_t sb = smBase + (uint32_t)(slot * STAGE_HALFS * 2);
        const int ko = kb * BK;
        cp16(sb + OFF_AH * 2 + dRow,         AH + gA0 + ko);
        cp16(sb + OFF_AH * 2 + dRow + dStep, AH + gA1 + ko);
        cp16(sb + OFF_BH * 2 + dRow,         BH + gB0 + ko);
        cp16(sb + OFF_BH * 2 + dRow + dStep, BH + gB1 + ko);
    };

#pragma unroll
    for (int s = 0; s < NSTAGE - 1; s++) {
        issue_stage(s, s);
        cp_commit();
    }

    for (int kb = 0; kb < KB; kb++) {
        const int slot = kb % NSTAGE;
        cp_wait<NSTAGE - 2>();
        __syncthreads();

        const uint32_t sb = smBase + (uint32_t)(slot * STAGE_HALFS * 2);
        const uint32_t tAh = sb + OFF_AH * 2;
        const uint32_t tBh = sb + OFF_BH * 2;

#pragma unroll
        for (int ks = 0; ks < 2; ks++) {
            uint32_t ah[2][4];
#pragma unroll
            for (int mt = 0; mt < 2; mt++) {
                uint32_t ao = aOffB + (uint32_t)(mt * 16 * LDA * 2 + ks * 32);
                ldsm_x4(ah[mt][0], ah[mt][1], ah[mt][2], ah[mt][3], tAh + ao);
            }
#pragma unroll
            for (int np = 0; np < 4; np++) {
                uint32_t bo = bOffB + (uint32_t)(np * 16 * LDA * 2 + ks * 32);
                uint32_t bh0, bh1, bh2, bh3;
                ldsm_x4(bh0, bh1, bh2, bh3, tBh + bo);
#pragma unroll
                for (int mt = 0; mt < 2; mt++) {
                    mma16816(acc[mt][2 * np + 0], ah[mt], bh0, bh1);
                    mma16816(acc[mt][2 * np + 1], ah[mt], bh2, bh3);
                }
            }
        }

        const int nk = kb + NSTAGE - 1;
        if (nk < KB) issue_stage(nk, nk % NSTAGE);
        cp_commit();
    }

    const int row0 = m0 + wm * 32 + (lane >> 2);
    const int col0 = n0 + wn * 64 + 2 * (lane & 3);
#pragma unroll
    for (int mt = 0; mt < 2; mt++) {
#pragma unroll
        for (int nt = 0; nt < 8; nt++) {
            float* p0 = C + (size_t)(row0 + mt * 16) * N + col0 + nt * 8;
            float* p1 = C + (size_t)(row0 + mt * 16 + 8) * N + col0 + nt * 8;
            *(float2*)p0 = make_float2(acc[mt][nt][0], acc[mt][nt][1]);
            *(float2*)p1 = make_float2(acc[mt][nt][2], acc[mt][nt][3]);
        }
    }
}

// ---------------------------------------------------------------------------
__global__ __launch_bounds__(256)
void split_kernel(const float* __restrict__ in, __half* __restrict__ hi,
                  __half* __restrict__ lo, unsigned n4)
{
    unsigned i = blockIdx.x * 256u + threadIdx.x;
    if (i >= n4) return;
    float4 v = ((const float4*)in)[i];
    __half h0 = __float2half_rn(v.x), h1 = __float2half_rn(v.y);
    __half h2 = __float2half_rn(v.z), h3 = __float2half_rn(v.w);
    __half l0 = __float2half_rn(v.x - __half2float(h0));
    __half l1 = __float2half_rn(v.y - __half2float(h1));
    __half l2 = __float2half_rn(v.z - __half2float(h2));
    __half l3 = __float2half_rn(v.w - __half2float(h3));
    uint2 hp, lp;
    hp.x = (uint32_t)__half_as_ushort(h0) | ((uint32_t)__half_as_ushort(h1) << 16);
    hp.y = (uint32_t)__half_as_ushort(h2) | ((uint32_t)__half_as_ushort(h3) << 16);
    lp.x = (uint32_t)__half_as_ushort(l0) | ((uint32_t)__half_as_ushort(l1) << 16);
    lp.y = (uint32_t)__half_as_ushort(l2) | ((uint32_t)__half_as_ushort(l3) << 16);
    ((uint2*)hi)[i] = hp;
    ((uint2*)lo)[i] = lp;
}

// ---------------------------------------------------------------------------
__global__ __launch_bounds__(256)
void transpose_half_kernel(const float* __restrict__ in,
                           __half* __restrict__ outH, int R, int C)
{
    __shared__ float tb[32][33];
    const int bz = blockIdx.z;
    in += (size_t)bz * R * C;
    const size_t ob = (size_t)bz * R * C;
    const int c0 = blockIdx.x * 32;
    const int r0 = blockIdx.y * 32;
    const int tx = threadIdx.x & 31;
    const int ty = threadIdx.x >> 5;
#pragma unroll
    for (int j = 0; j < 32; j += 8)
        tb[ty + j][tx] = in[(size_t)(r0 + ty + j) * C + c0 + tx];
    __syncthreads();
#pragma unroll
    for (int j = 0; j < 32; j += 8) {
        float v = tb[tx][ty + j];
        outH[ob + (size_t)(c0 + ty + j) * R + r0 + tx] = __float2half_rn(v);
    }
}

// ---------------------------------------------------------------------------
__global__ __launch_bounds__(256)
void softmax_rows_kernel(float* __restrict__ W, __half* __restrict__ WH)
{
    const int Tk = 2048;
    const size_t base = (size_t)blockIdx.x * Tk;
    float4* p4 = (float4*)(W + base);
    uint2* ph2 = (uint2*)(WH + base);
    const int tid = threadIdx.x;

    __shared__ float red[8];

    float4 v0 = p4[tid];
    float4 v1 = p4[tid + 256];
    float m = fmaxf(fmaxf(fmaxf(v0.x, v0.y), fmaxf(v0.z, v0.w)),
                    fmaxf(fmaxf(v1.x, v1.y), fmaxf(v1.z, v1.w)));
#pragma unroll
    for (int o = 16; o; o >>= 1) m = fmaxf(m, __shfl_xor_sync(0xffffffffu, m, o));
    if ((tid & 31) == 0) red[tid >> 5] = m;
    __syncthreads();
    m = red[0];
#pragma unroll
    for (int w = 1; w < 8; w++) m = fmaxf(m, red[w]);
    __syncthreads();

    v0.x = __expf(v0.x - m); v0.y = __expf(v0.y - m);
    v0.z = __expf(v0.z - m); v0.w = __expf(v0.w - m);
    v1.x = __expf(v1.x - m); v1.y = __expf(v1.y - m);
    v1.z = __expf(v1.z - m); v1.w = __expf(v1.w - m);
    float s = (v0.x + v0.y) + (v0.z + v0.w) + (v1.x + v1.y) + (v1.z + v1.w);
#pragma unroll
    for (int o = 16; o; o >>= 1) s += __shfl_xor_sync(0xffffffffu, s, o);
    if ((tid & 31) == 0) red[tid >> 5] = s;
    __syncthreads();
    s = red[0];
#pragma unroll
    for (int w = 1; w < 8; w++) s += red[w];
    const float inv = 1.0f / s;

    v0.x *= inv; v0.y *= inv; v0.z *= inv; v0.w *= inv;
    v1.x *= inv; v1.y *= inv; v1.z *= inv; v1.w *= inv;
    p4[tid] = v0;
    p4[tid + 256] = v1;

    __half2 a0 = __floats2half2_rn(v0.x, v0.y);
    __half2 a1 = __floats2half2_rn(v0.z, v0.w);
    __half2 a2 = __floats2half2_rn(v1.x, v1.y);
    __half2 a3 = __floats2half2_rn(v1.z, v1.w);
    ph2[tid]       = make_uint2(*(uint32_t*)&a0, *(uint32_t*)&a1);
    ph2[tid + 256] = make_uint2(*(uint32_t*)&a2, *(uint32_t*)&a3);
}

// ---------------------------------------------------------------------------
extern "C" void kernel_launch(void* const* d_in, const int* in_sizes, int n_in,
                              void* d_out, int out_size)
{
    const float* dec = (const float*)d_in[0];  // [8, 2048, 1024]
    const float* enc = (const float*)d_in[1];  // [8, 2048, 1024]

    const int B = 8, Tq = 2048, Tk = 2048, D = 1024;

    float* ctx = (float*)d_out;                          // [B, Tq, D]
    float* wts = (float*)d_out + (size_t)B * Tq * D;     // [B, Tq, Tk]

    __half *decH, *decL, *encH, *encL, *encTH, *wtsH;
    cudaGetSymbolAddress((void**)&decH, g_decH);
    cudaGetSymbolAddress((void**)&decL, g_decL);
    cudaGetSymbolAddress((void**)&encH, g_encH);
    cudaGetSymbolAddress((void**)&encL, g_encL);
    cudaGetSymbolAddress((void**)&encTH, g_encTH);
    cudaGetSymbolAddress((void**)&wtsH, g_wtsH);

    constexpr int SMEM3 = 3 * (2 * A_HALFS + 2 * B_HALFS) * 2;  // 184320
    constexpr int SMEM2 = 5 * (A_HALFS + B2_HALFS) * 2;         // 102400
    cudaFuncSetAttribute((const void*)hmma_gemm1,
                         cudaFuncAttributeMaxDynamicSharedMemorySize, SMEM3);
    cudaFuncSetAttribute((const void*)hmma_gemm2,
                         cudaFuncAttributeMaxDynamicSharedMemorySize, SMEM2);

    const unsigned n4 = NELEM / 4;

    // 0) pre-split operands
    split_kernel<<<(n4 + 255) / 256, 256>>>(dec, decH, decL, n4);
    split_kernel<<<(n4 + 255) / 256, 256>>>(enc, encH, encL, n4);
    transpose_half_kernel<<<dim3(D / 32, Tk / 32, B), 256>>>(enc, encTH, Tk, D);

    // 1) scores = dec @ enc^T  (3-term)
    hmma_gemm1<<<dim3(Tk / BN, Tq / BM, B), 512, SMEM3>>>(
        decH, decL, encH, encL, wts, Tq, Tk, D);

    // 2) softmax in place (+ fp16 weights)
    softmax_rows_kernel<<<B * Tq, 256>>>(wts, wtsH);

    // 3) context = weights @ enc  (1-term, BN=128, 2 CTAs/SM)
    hmma_gemm2<<<dim3(D / 128, Tq / BM, B), 256, SMEM2>>>(
        wtsH, encTH, ctx, Tq, D, Tk);
}